// round 1
// baseline (speedup 1.0000x reference)
#include <cuda_runtime.h>
#include <cuda_bf16.h>
#include <math.h>

// ---------------------------------------------------------------------------
// Problem constants
// ---------------------------------------------------------------------------
#define B_     2
#define T_     20
#define V_     256
#define TN     (T_ * V_)          // 5120 rows per batch
#define NROWS  (B_ * TN)          // 10240
#define HID    4
#define DQ     8
#define OUTD   5
#define CMAP   2048
#define HMAP   32
#define WMAP   32
#define NPIX   (HMAP * WMAP)      // 1024
#define CC     256

#define KSPLIT 16
#define KCHUNK (TN / KSPLIT)      // 320

// ---------------------------------------------------------------------------
// Device-global scratch (no cudaMalloc allowed)
// ---------------------------------------------------------------------------
__device__ float  g_Weff[4 * CMAP];          // W_fuse[:,4:] @ W_comp   (4 x 2048)
__device__ float  g_cb[4];                   // W_fuse[:,4:] @ b_comp
__device__ float  g_pp[8 * 4 * NPIX];        // split-K partials of pcomp
__device__ float4 g_pcomp4[NPIX];            // projected 4-ch map, [pix](h0..h3)
__device__ float  g_Q[NROWS * DQ];
__device__ float  g_KV[NROWS * 16];          // K(8) | V(8) interleaved per row
__device__ float  g_part[KSPLIT * NROWS * DQ]; // attention partial sums

// ---------------------------------------------------------------------------
// K0: Weff[h][c] = sum_cc W_fuse[h][4+cc] * W_comp[cc][c];  cb[h] = Wf_l @ b_comp
// grid(8) x 256: block bx covers c in [bx*256, bx*256+256)
// ---------------------------------------------------------------------------
__global__ void k0_weff(const float* __restrict__ W_fuse,
                        const float* __restrict__ W_comp,
                        const float* __restrict__ b_comp) {
    __shared__ float sw[4 * CC];
    int tid = threadIdx.x;
    for (int i = tid; i < 4 * CC; i += 256) {
        int h = i >> 8, cc = i & 255;
        sw[i] = W_fuse[h * 260 + 4 + cc];
    }
    __syncthreads();

    int c = blockIdx.x * 256 + tid;
    float a0 = 0.f, a1 = 0.f, a2 = 0.f, a3 = 0.f;
#pragma unroll 8
    for (int cc = 0; cc < CC; cc++) {
        float w = W_comp[cc * CMAP + c];
        a0 += sw[cc]        * w;
        a1 += sw[256 + cc]  * w;
        a2 += sw[512 + cc]  * w;
        a3 += sw[768 + cc]  * w;
    }
    g_Weff[0 * CMAP + c] = a0;
    g_Weff[1 * CMAP + c] = a1;
    g_Weff[2 * CMAP + c] = a2;
    g_Weff[3 * CMAP + c] = a3;

    if (blockIdx.x == 0 && tid < 32) {
        float p0 = 0.f, p1 = 0.f, p2 = 0.f, p3 = 0.f;
        for (int cc = tid; cc < CC; cc += 32) {
            float bv = b_comp[cc];
            p0 += sw[cc]       * bv;
            p1 += sw[256 + cc] * bv;
            p2 += sw[512 + cc] * bv;
            p3 += sw[768 + cc] * bv;
        }
#pragma unroll
        for (int o = 16; o > 0; o >>= 1) {
            p0 += __shfl_down_sync(0xffffffffu, p0, o);
            p1 += __shfl_down_sync(0xffffffffu, p1, o);
            p2 += __shfl_down_sync(0xffffffffu, p2, o);
            p3 += __shfl_down_sync(0xffffffffu, p3, o);
        }
        if (tid == 0) { g_cb[0] = p0; g_cb[1] = p1; g_cb[2] = p2; g_cb[3] = p3; }
    }
}

// ---------------------------------------------------------------------------
// K1: pcomp partials: pp[cg][h][pix] = sum_{cl} Weff[h][cg*256+cl] * m[cg*256+cl][pix]
// grid(4, 8) x 256 : bx = pixel group of 256, by = c chunk of 256
// ---------------------------------------------------------------------------
__global__ void k1_pcomp_part(const float* __restrict__ metadata) {
    __shared__ float sw[4 * 256];
    int tid = threadIdx.x;
    int cg = blockIdx.y;
    for (int i = tid; i < 4 * 256; i += 256) {
        int h = i >> 8, cl = i & 255;
        sw[i] = g_Weff[h * CMAP + cg * 256 + cl];
    }
    __syncthreads();

    int pix = blockIdx.x * 256 + tid;
    float a0 = 0.f, a1 = 0.f, a2 = 0.f, a3 = 0.f;
#pragma unroll 8
    for (int cl = 0; cl < 256; cl++) {
        float m = metadata[(cg * 256 + cl) * NPIX + pix];
        a0 += sw[cl]        * m;
        a1 += sw[256 + cl]  * m;
        a2 += sw[512 + cl]  * m;
        a3 += sw[768 + cl]  * m;
    }
    g_pp[((cg * 4) + 0) * NPIX + pix] = a0;
    g_pp[((cg * 4) + 1) * NPIX + pix] = a1;
    g_pp[((cg * 4) + 2) * NPIX + pix] = a2;
    g_pp[((cg * 4) + 3) * NPIX + pix] = a3;
}

// ---------------------------------------------------------------------------
// K1b: reduce 8 partials + bias -> g_pcomp4[pix] = (h0,h1,h2,h3)
// grid(4) x 256
// ---------------------------------------------------------------------------
__global__ void k1b_reduce() {
    int pix = blockIdx.x * 256 + threadIdx.x;
    float s0 = g_cb[0], s1 = g_cb[1], s2 = g_cb[2], s3 = g_cb[3];
#pragma unroll
    for (int cg = 0; cg < 8; cg++) {
        s0 += g_pp[(cg * 4 + 0) * NPIX + pix];
        s1 += g_pp[(cg * 4 + 1) * NPIX + pix];
        s2 += g_pp[(cg * 4 + 2) * NPIX + pix];
        s3 += g_pp[(cg * 4 + 3) * NPIX + pix];
    }
    g_pcomp4[pix] = make_float4(s0, s1, s2, s3);
}

// ---------------------------------------------------------------------------
// K2: per-row: pos-encode, LSTM step, bilinear sample of 4-ch map, fuse, Q/K/V.
// grid(40) x 256, one thread per row.
// ---------------------------------------------------------------------------
__device__ __forceinline__ float sigm_acc(float x) { return 1.f / (1.f + expf(-x)); }

__global__ void k2_rows(const float* __restrict__ x,
                        const float* __restrict__ coords,
                        const float* __restrict__ W_ih,
                        const float* __restrict__ b_ih,
                        const float* __restrict__ b_hh,
                        const float* __restrict__ W_fuse,
                        const float* __restrict__ b_fuse,
                        const float* __restrict__ W_fc,
                        const float* __restrict__ b_fc,
                        const float* __restrict__ W_fc2,
                        const float* __restrict__ b_fc2,
                        const float* __restrict__ W_fc3,
                        const float* __restrict__ b_fc3) {
    int r = blockIdx.x * 256 + threadIdx.x;
    if (r >= NROWS) return;
    int b = r / TN;
    int p = r - b * TN;
    int t = p / V_;
    int v = p - t * V_;

    float tf  = (float)t;
    float xr0 = x[r * 2 + 0] + sinf(tf);
    float xr1 = x[r * 2 + 1] + cosf(tf);

    // single-step LSTM (h0=c0=0), gate order i,f,g,o; f unused.
    float X[HID];
#pragma unroll
    for (int h = 0; h < HID; h++) {
        int ji = h, jg = 8 + h, jo = 12 + h;
        float gi = W_ih[ji * 2] * xr0 + W_ih[ji * 2 + 1] * xr1 + b_ih[ji] + b_hh[ji];
        float gg = W_ih[jg * 2] * xr0 + W_ih[jg * 2 + 1] * xr1 + b_ih[jg] + b_hh[jg];
        float go = W_ih[jo * 2] * xr0 + W_ih[jo * 2 + 1] * xr1 + b_ih[jo] + b_hh[jo];
        float cst = sigm_acc(gi) * tanhf(gg);
        X[h] = sigm_acc(go) * tanhf(cst);
    }

    // bilinear sample of pre-projected 4-channel map (align_corners=False, zero pad)
    float cx = coords[((b * 2 + 0) * T_ + t) * V_ + v];
    float cy = coords[((b * 2 + 1) * T_ + t) * V_ + v];
    float fx = cx * (1.f / 16.f) - 0.5f;
    float fy = cy * (1.f / 16.f) - 0.5f;
    float x0f = floorf(fx), y0f = floorf(fy);
    int ix0 = (int)x0f, iy0 = (int)y0f;
    float wx1 = fx - x0f, wx0 = 1.f - wx1;
    float wy1 = fy - y0f, wy0 = 1.f - wy1;

    float l0 = 0.f, l1 = 0.f, l2 = 0.f, l3 = 0.f;
#pragma unroll
    for (int cyi = 0; cyi < 2; cyi++) {
#pragma unroll
        for (int cxi = 0; cxi < 2; cxi++) {
            int iy = iy0 + cyi, ix = ix0 + cxi;
            if (iy >= 0 && iy < HMAP && ix >= 0 && ix < WMAP) {
                float w = (cyi ? wy1 : wy0) * (cxi ? wx1 : wx0);
                float4 pv = g_pcomp4[iy * WMAP + ix];
                l0 += w * pv.x; l1 += w * pv.y; l2 += w * pv.z; l3 += w * pv.w;
            }
        }
    }

    // fuse: X part through W_fuse[:, :4], local part already projected.
    float fsd[HID];
#pragma unroll
    for (int h = 0; h < HID; h++) {
        float s = b_fuse[h];
#pragma unroll
        for (int j = 0; j < HID; j++) s += W_fuse[h * 260 + j] * X[j];
        fsd[h] = s + (h == 0 ? l0 : (h == 1 ? l1 : (h == 2 ? l2 : l3)));
    }

    // Q from fused, K/V from pos-encoded input
#pragma unroll
    for (int d = 0; d < DQ; d++) {
        float q = b_fc[d];
#pragma unroll
        for (int h = 0; h < HID; h++) q += W_fc[d * HID + h] * fsd[h];
        g_Q[r * DQ + d] = q;
        g_KV[r * 16 + d]     = W_fc2[d * 2] * xr0 + W_fc2[d * 2 + 1] * xr1 + b_fc2[d];
        g_KV[r * 16 + 8 + d] = W_fc3[d * 2] * xr0 + W_fc3[d * 2 + 1] * xr1 + b_fc3[d];
    }
}

// ---------------------------------------------------------------------------
// K3: fused sigmoid attention, key-split partials.
// grid(40, KSPLIT) x 256. block bx handles queries [bx*256, +256) (within one
// batch since TN/256 = 20), ks handles keys [ks*KCHUNK, +KCHUNK) of that batch.
// ---------------------------------------------------------------------------
__global__ void k3_attn() {
    __shared__ float4 skv[KCHUNK * 4];   // 20 KB: K0,K1,V0,V1 per key
    int bx  = blockIdx.x;
    int ks  = blockIdx.y;
    int tid = threadIdx.x;
    int b   = bx / 20;

    const float4* src = (const float4*)(g_KV + (size_t)(b * TN + ks * KCHUNK) * 16);
#pragma unroll
    for (int i = tid; i < KCHUNK * 4; i += 256) skv[i] = src[i];
    __syncthreads();

    int r = bx * 256 + tid;
    const float4* qp = (const float4*)(g_Q + (size_t)r * DQ);
    float4 q0 = qp[0], q1 = qp[1];
    float4 a0 = make_float4(0.f, 0.f, 0.f, 0.f);
    float4 a1 = make_float4(0.f, 0.f, 0.f, 0.f);

#pragma unroll 4
    for (int j = 0; j < KCHUNK; j++) {
        float4 k0 = skv[j * 4 + 0];
        float4 k1 = skv[j * 4 + 1];
        float4 v0 = skv[j * 4 + 2];
        float4 v1 = skv[j * 4 + 3];
        float d = q0.x * k0.x + q0.y * k0.y + q0.z * k0.z + q0.w * k0.w
                + q1.x * k1.x + q1.y * k1.y + q1.z * k1.z + q1.w * k1.w;
        float e = __expf(-d);                      // FMUL + MUFU.EX2
        float pr = __fdividef(1.f, 1.f + e);       // FADD + MUFU.RCP
        a0.x += pr * v0.x; a0.y += pr * v0.y; a0.z += pr * v0.z; a0.w += pr * v0.w;
        a1.x += pr * v1.x; a1.y += pr * v1.y; a1.z += pr * v1.z; a1.w += pr * v1.w;
    }

    float4* dst = (float4*)(g_part + ((size_t)ks * NROWS + r) * DQ);
    dst[0] = a0;
    dst[1] = a1;
}

// ---------------------------------------------------------------------------
// K4: reduce partials, threshold-relu, output projection, transpose-store.
// grid(40) x 256.
// ---------------------------------------------------------------------------
__global__ void k4_out(const float* __restrict__ W_out,
                       const float* __restrict__ b_out,
                       float* __restrict__ out) {
    int r = blockIdx.x * 256 + threadIdx.x;
    if (r >= NROWS) return;

    float4 s0 = make_float4(0.f, 0.f, 0.f, 0.f);
    float4 s1 = make_float4(0.f, 0.f, 0.f, 0.f);
#pragma unroll
    for (int ksi = 0; ksi < KSPLIT; ksi++) {
        const float4* p = (const float4*)(g_part + ((size_t)ksi * NROWS + r) * DQ);
        float4 x0 = p[0], x1 = p[1];
        s0.x += x0.x; s0.y += x0.y; s0.z += x0.z; s0.w += x0.w;
        s1.x += x1.x; s1.y += x1.y; s1.z += x1.z; s1.w += x1.w;
    }
    float s[DQ] = { s0.x, s0.y, s0.z, s0.w, s1.x, s1.y, s1.z, s1.w };
#pragma unroll
    for (int d = 0; d < DQ; d++) s[d] = (s[d] > 0.5f) ? s[d] : 0.f;

    int b = r / TN;
    int p = r - b * TN;
    int t = p / V_;
    int v = p - t * V_;

#pragma unroll
    for (int d = 0; d < OUTD; d++) {
        float y = b_out[d];
#pragma unroll
        for (int h = 0; h < DQ; h++) y += W_out[d * DQ + h] * s[h];
        out[((b * OUTD + d) * T_ + t) * V_ + v] = y;
    }
}

// ---------------------------------------------------------------------------
// Launch
// ---------------------------------------------------------------------------
extern "C" void kernel_launch(void* const* d_in, const int* in_sizes, int n_in,
                              void* d_out, int out_size) {
    const float* x       = (const float*)d_in[0];
    const float* coords  = (const float*)d_in[1];
    const float* meta    = (const float*)d_in[2];
    const float* W_ih    = (const float*)d_in[3];
    /* W_hh (d_in[4]) unused: h0 = 0 */
    const float* b_ih    = (const float*)d_in[5];
    const float* b_hh    = (const float*)d_in[6];
    const float* W_comp  = (const float*)d_in[7];
    const float* b_comp  = (const float*)d_in[8];
    const float* W_fuse  = (const float*)d_in[9];
    const float* b_fuse  = (const float*)d_in[10];
    const float* W_fc    = (const float*)d_in[11];
    const float* b_fc    = (const float*)d_in[12];
    const float* W_fc2   = (const float*)d_in[13];
    const float* b_fc2   = (const float*)d_in[14];
    const float* W_fc3   = (const float*)d_in[15];
    const float* b_fc3   = (const float*)d_in[16];
    const float* W_out   = (const float*)d_in[17];
    const float* b_out   = (const float*)d_in[18];
    float* out = (float*)d_out;

    k0_weff<<<8, 256>>>(W_fuse, W_comp, b_comp);
    k1_pcomp_part<<<dim3(4, 8), 256>>>(meta);
    k1b_reduce<<<4, 256>>>();
    k2_rows<<<40, 256>>>(x, coords, W_ih, b_ih, b_hh, W_fuse, b_fuse,
                         W_fc, b_fc, W_fc2, b_fc2, W_fc3, b_fc3);
    k3_attn<<<dim3(40, KSPLIT), 256>>>();
    k4_out<<<40, 256>>>(W_out, b_out, out);
}

// round 4
// speedup vs baseline: 1.0797x; 1.0797x over previous
#include <cuda_runtime.h>
#include <cuda_bf16.h>
#include <math.h>

// ---------------------------------------------------------------------------
// Problem constants
// ---------------------------------------------------------------------------
#define B_     2
#define T_     20
#define V_     256
#define TN     (T_ * V_)          // 5120 rows per batch
#define NROWS  (B_ * TN)          // 10240
#define HID    4
#define DQ     8
#define OUTD   5
#define CMAP   2048
#define HMAP   32
#define WMAP   32
#define NPIX   (HMAP * WMAP)      // 1024
#define CC     256

#define KSPLIT 16
#define KCHUNK (TN / KSPLIT)      // 320
#define QBLK   512                // queries per k3 block (128 thr x 4 q)
#define NQB    (NROWS / QBLK)     // 20

// ---------------------------------------------------------------------------
// Device-global scratch
// ---------------------------------------------------------------------------
__device__ float  g_Weffp[4 * 4 * CMAP];       // 4 cc-split partials of Weff
__device__ float  g_cb[4];                     // W_fuse[:,4:] @ b_comp
__device__ float  g_pp[32 * 4 * NPIX];         // 32 ch-split partials of pcomp
__device__ float4 g_pcomp4[NPIX];              // projected 4-ch map
__device__ float  g_Q[NROWS * DQ];             // Q pre-scaled by -log2(e)
__device__ float  g_KV[NROWS * 16];            // K(8) | V(8) per row
__device__ float  g_part[KSPLIT * NROWS * DQ]; // attention partials

// ---------------------------------------------------------------------------
// approx-math helpers (plain MUFU ops only — no packed f32x2)
// ---------------------------------------------------------------------------
__device__ __forceinline__ float ex2f(float x) {
    float r; asm("ex2.approx.f32 %0, %1;" : "=f"(r) : "f"(x)); return r;
}
__device__ __forceinline__ float rcpf(float x) {
    float r; asm("rcp.approx.f32 %0, %1;" : "=f"(r) : "f"(x)); return r;
}
__device__ __forceinline__ float fsigm(float x) {      // 1/(1+e^-x)
    return rcpf(1.f + ex2f(-1.44269504f * x));
}
__device__ __forceinline__ float ftanh(float x) {      // 1 - 2/(e^2x+1)
    return 1.f - 2.f * rcpf(ex2f(2.88539008f * x) + 1.f);
}

// ---------------------------------------------------------------------------
// K0: partial Weff: g_Weffp[s][h][c] = sum_{cc in split s} Wf_l[h][cc]*W_comp[cc][c]
// grid(8, 4) x 256
// ---------------------------------------------------------------------------
__global__ __launch_bounds__(256) void k0_weff(const float* __restrict__ W_fuse,
                                               const float* __restrict__ W_comp,
                                               const float* __restrict__ b_comp) {
    __shared__ float sw[4 * 64];
    int tid = threadIdx.x, by = blockIdx.y;
    if (tid < 256) {
        int h = tid >> 6, cc = tid & 63;
        sw[tid] = W_fuse[h * 260 + 4 + by * 64 + cc];
    }
    __syncthreads();

    int c = blockIdx.x * 256 + tid;
    float a0 = 0.f, a1 = 0.f, a2 = 0.f, a3 = 0.f;
#pragma unroll 8
    for (int cc = 0; cc < 64; cc++) {
        float w = W_comp[(by * 64 + cc) * CMAP + c];
        a0 += sw[cc]       * w;
        a1 += sw[64 + cc]  * w;
        a2 += sw[128 + cc] * w;
        a3 += sw[192 + cc] * w;
    }
    g_Weffp[(by * 4 + 0) * CMAP + c] = a0;
    g_Weffp[(by * 4 + 1) * CMAP + c] = a1;
    g_Weffp[(by * 4 + 2) * CMAP + c] = a2;
    g_Weffp[(by * 4 + 3) * CMAP + c] = a3;

    if (blockIdx.x == 0 && by == 0 && tid < 32) {
        float p0 = 0.f, p1 = 0.f, p2 = 0.f, p3 = 0.f;
        for (int cc = tid; cc < CC; cc += 32) {
            float bv = b_comp[cc];
            p0 += W_fuse[0 * 260 + 4 + cc] * bv;
            p1 += W_fuse[1 * 260 + 4 + cc] * bv;
            p2 += W_fuse[2 * 260 + 4 + cc] * bv;
            p3 += W_fuse[3 * 260 + 4 + cc] * bv;
        }
#pragma unroll
        for (int o = 16; o > 0; o >>= 1) {
            p0 += __shfl_down_sync(0xffffffffu, p0, o);
            p1 += __shfl_down_sync(0xffffffffu, p1, o);
            p2 += __shfl_down_sync(0xffffffffu, p2, o);
            p3 += __shfl_down_sync(0xffffffffu, p3, o);
        }
        if (tid == 0) { g_cb[0] = p0; g_cb[1] = p1; g_cb[2] = p2; g_cb[3] = p3; }
    }
}

// ---------------------------------------------------------------------------
// K1: partial pcomp over 64-channel chunks. grid(32) x 256.
// ---------------------------------------------------------------------------
__global__ __launch_bounds__(256) void k1_pcomp(const float* __restrict__ metadata) {
    __shared__ float sw[256];   // [h*64 + cl], summed over 4 Weff partials
    int tid = threadIdx.x, ci = blockIdx.x;
    if (tid < 256) {
        int h = tid >> 6, cl = tid & 63;
        int c = ci * 64 + cl;
        float s = g_Weffp[(0 * 4 + h) * CMAP + c] + g_Weffp[(1 * 4 + h) * CMAP + c]
                + g_Weffp[(2 * 4 + h) * CMAP + c] + g_Weffp[(3 * 4 + h) * CMAP + c];
        sw[tid] = s;
    }
    __syncthreads();

    const float4* m4 = (const float4*)metadata;
    float4 a0 = make_float4(0, 0, 0, 0), a1 = a0, a2 = a0, a3 = a0;
#pragma unroll 8
    for (int cl = 0; cl < 64; cl++) {
        float4 m = m4[(ci * 64 + cl) * 256 + tid];
        float w0 = sw[cl], w1 = sw[64 + cl], w2 = sw[128 + cl], w3 = sw[192 + cl];
        a0.x += w0 * m.x; a0.y += w0 * m.y; a0.z += w0 * m.z; a0.w += w0 * m.w;
        a1.x += w1 * m.x; a1.y += w1 * m.y; a1.z += w1 * m.z; a1.w += w1 * m.w;
        a2.x += w2 * m.x; a2.y += w2 * m.y; a2.z += w2 * m.z; a2.w += w2 * m.w;
        a3.x += w3 * m.x; a3.y += w3 * m.y; a3.z += w3 * m.z; a3.w += w3 * m.w;
    }
    float4* pp4 = (float4*)g_pp;
    pp4[(ci * 4 + 0) * 256 + tid] = a0;
    pp4[(ci * 4 + 1) * 256 + tid] = a1;
    pp4[(ci * 4 + 2) * 256 + tid] = a2;
    pp4[(ci * 4 + 3) * 256 + tid] = a3;
}

// ---------------------------------------------------------------------------
// K1b: reduce 32 partials + bias -> g_pcomp4. grid(4) x 256.
// ---------------------------------------------------------------------------
__global__ __launch_bounds__(256) void k1b_reduce() {
    int pix = blockIdx.x * 256 + threadIdx.x;
    float s0 = g_cb[0], s1 = g_cb[1], s2 = g_cb[2], s3 = g_cb[3];
#pragma unroll 8
    for (int ci = 0; ci < 32; ci++) {
        s0 += g_pp[(ci * 4 + 0) * NPIX + pix];
        s1 += g_pp[(ci * 4 + 1) * NPIX + pix];
        s2 += g_pp[(ci * 4 + 2) * NPIX + pix];
        s3 += g_pp[(ci * 4 + 3) * NPIX + pix];
    }
    g_pcomp4[pix] = make_float4(s0, s1, s2, s3);
}

// ---------------------------------------------------------------------------
// K2: per-row pos-encode, LSTM, bilinear sample, fuse, Q/K/V. grid(80) x 128.
// Q is stored pre-scaled by -log2(e) so k3's sigmoid needs no extra FMUL.
// ---------------------------------------------------------------------------
__global__ __launch_bounds__(128) void k2_rows(
        const float* __restrict__ x,
        const float* __restrict__ coords,
        const float* __restrict__ W_ih,
        const float* __restrict__ b_ih,
        const float* __restrict__ b_hh,
        const float* __restrict__ W_fuse,
        const float* __restrict__ b_fuse,
        const float* __restrict__ W_fc,
        const float* __restrict__ b_fc,
        const float* __restrict__ W_fc2,
        const float* __restrict__ b_fc2,
        const float* __restrict__ W_fc3,
        const float* __restrict__ b_fc3) {
    int r = blockIdx.x * 128 + threadIdx.x;
    if (r >= NROWS) return;
    int b = r / TN;
    int p = r - b * TN;
    int t = p / V_;
    int v = p - t * V_;

    float tf  = (float)t;
    float xr0 = x[r * 2 + 0] + __sinf(tf);
    float xr1 = x[r * 2 + 1] + __cosf(tf);

    float X[HID];
#pragma unroll
    for (int h = 0; h < HID; h++) {
        int ji = h, jg = 8 + h, jo = 12 + h;
        float gi = W_ih[ji * 2] * xr0 + W_ih[ji * 2 + 1] * xr1 + b_ih[ji] + b_hh[ji];
        float gg = W_ih[jg * 2] * xr0 + W_ih[jg * 2 + 1] * xr1 + b_ih[jg] + b_hh[jg];
        float go = W_ih[jo * 2] * xr0 + W_ih[jo * 2 + 1] * xr1 + b_ih[jo] + b_hh[jo];
        float cst = fsigm(gi) * ftanh(gg);
        X[h] = fsigm(go) * ftanh(cst);
    }

    float cx = coords[((b * 2 + 0) * T_ + t) * V_ + v];
    float cy = coords[((b * 2 + 1) * T_ + t) * V_ + v];
    float fx = cx * (1.f / 16.f) - 0.5f;
    float fy = cy * (1.f / 16.f) - 0.5f;
    float x0f = floorf(fx), y0f = floorf(fy);
    int ix0 = (int)x0f, iy0 = (int)y0f;
    float wx1 = fx - x0f, wx0 = 1.f - wx1;
    float wy1 = fy - y0f, wy0 = 1.f - wy1;

    float l0 = 0.f, l1 = 0.f, l2 = 0.f, l3 = 0.f;
#pragma unroll
    for (int cyi = 0; cyi < 2; cyi++) {
#pragma unroll
        for (int cxi = 0; cxi < 2; cxi++) {
            int iy = iy0 + cyi, ix = ix0 + cxi;
            if (iy >= 0 && iy < HMAP && ix >= 0 && ix < WMAP) {
                float w = (cyi ? wy1 : wy0) * (cxi ? wx1 : wx0);
                float4 pv = g_pcomp4[iy * WMAP + ix];
                l0 += w * pv.x; l1 += w * pv.y; l2 += w * pv.z; l3 += w * pv.w;
            }
        }
    }

    float fsd[HID];
#pragma unroll
    for (int h = 0; h < HID; h++) {
        float s = b_fuse[h];
#pragma unroll
        for (int j = 0; j < HID; j++) s += W_fuse[h * 260 + j] * X[j];
        fsd[h] = s + (h == 0 ? l0 : (h == 1 ? l1 : (h == 2 ? l2 : l3)));
    }

#pragma unroll
    for (int d = 0; d < DQ; d++) {
        float q = b_fc[d];
#pragma unroll
        for (int h = 0; h < HID; h++) q += W_fc[d * HID + h] * fsd[h];
        g_Q[r * DQ + d] = q * -1.44269504f;   // fold -log2(e) into Q
        g_KV[r * 16 + d]     = W_fc2[d * 2] * xr0 + W_fc2[d * 2 + 1] * xr1 + b_fc2[d];
        g_KV[r * 16 + 8 + d] = W_fc3[d * 2] * xr0 + W_fc3[d * 2 + 1] * xr1 + b_fc3[d];
    }
}

// ---------------------------------------------------------------------------
// K3: fused sigmoid attention, scalar fp32, 4 queries/thread.
// grid(NQB=20, KSPLIT=16) x 128. smem 20 KB: 4 float4 per key (k0,k1,v0,v1).
// pr = rcp(1 + ex2(qs . k))  where qs already carries the -log2e factor.
// ---------------------------------------------------------------------------
__global__ __launch_bounds__(128) void k3_attn() {
    __shared__ float4 skv[KCHUNK * 4];
    int bq  = blockIdx.x;
    int ks  = blockIdx.y;
    int tid = threadIdx.x;
    int b   = bq / (NQB / B_);
    int kbase = b * TN + ks * KCHUNK;

    const float4* src = (const float4*)(g_KV + (size_t)kbase * 16);
#pragma unroll
    for (int i = tid; i < KCHUNK * 4; i += 128) skv[i] = src[i];
    __syncthreads();

    int r = bq * QBLK + tid * 4;

    float q[4][8];
    const float4* qv = (const float4*)(g_Q + (size_t)r * DQ);
#pragma unroll
    for (int i = 0; i < 4; i++) {
        float4 a = qv[i * 2 + 0], bb = qv[i * 2 + 1];
        q[i][0] = a.x;  q[i][1] = a.y;  q[i][2] = a.z;  q[i][3] = a.w;
        q[i][4] = bb.x; q[i][5] = bb.y; q[i][6] = bb.z; q[i][7] = bb.w;
    }

    float acc[4][8];
#pragma unroll
    for (int i = 0; i < 4; i++)
#pragma unroll
        for (int d = 0; d < 8; d++) acc[i][d] = 0.f;

#pragma unroll 2
    for (int j = 0; j < KCHUNK; j++) {
        float4 k0 = skv[j * 4 + 0];
        float4 k1 = skv[j * 4 + 1];
        float kk[8] = { k0.x, k0.y, k0.z, k0.w, k1.x, k1.y, k1.z, k1.w };

        float pr[4];
#pragma unroll
        for (int i = 0; i < 4; i++) {
            float d = q[i][0] * kk[0];
#pragma unroll
            for (int dd = 1; dd < 8; dd++) d += q[i][dd] * kk[dd];
            pr[i] = rcpf(1.f + ex2f(d));
        }

        float4 v0 = skv[j * 4 + 2];
        float4 v1 = skv[j * 4 + 3];
        float vv[8] = { v0.x, v0.y, v0.z, v0.w, v1.x, v1.y, v1.z, v1.w };
#pragma unroll
        for (int i = 0; i < 4; i++)
#pragma unroll
            for (int dd = 0; dd < 8; dd++) acc[i][dd] += pr[i] * vv[dd];
    }

    float4* dst = (float4*)(g_part + ((size_t)ks * NROWS + r) * DQ);
#pragma unroll
    for (int i = 0; i < 4; i++) {
        dst[i * 2 + 0] = make_float4(acc[i][0], acc[i][1], acc[i][2], acc[i][3]);
        dst[i * 2 + 1] = make_float4(acc[i][4], acc[i][5], acc[i][6], acc[i][7]);
    }
}

// ---------------------------------------------------------------------------
// K4: reduce partials, threshold, out projection, transpose store. grid(80)x128
// ---------------------------------------------------------------------------
__global__ __launch_bounds__(128) void k4_out(const float* __restrict__ W_out,
                                              const float* __restrict__ b_out,
                                              float* __restrict__ out) {
    int r = blockIdx.x * 128 + threadIdx.x;
    if (r >= NROWS) return;

    float4 s0 = make_float4(0, 0, 0, 0), s1 = s0;
#pragma unroll
    for (int ksi = 0; ksi < KSPLIT; ksi++) {
        const float4* p = (const float4*)(g_part + ((size_t)ksi * NROWS + r) * DQ);
        float4 x0 = p[0], x1 = p[1];
        s0.x += x0.x; s0.y += x0.y; s0.z += x0.z; s0.w += x0.w;
        s1.x += x1.x; s1.y += x1.y; s1.z += x1.z; s1.w += x1.w;
    }
    float s[DQ] = { s0.x, s0.y, s0.z, s0.w, s1.x, s1.y, s1.z, s1.w };
#pragma unroll
    for (int d = 0; d < DQ; d++) s[d] = (s[d] > 0.5f) ? s[d] : 0.f;

    int b = r / TN;
    int p = r - b * TN;
    int t = p / V_;
    int v = p - t * V_;

#pragma unroll
    for (int d = 0; d < OUTD; d++) {
        float y = b_out[d];
#pragma unroll
        for (int h = 0; h < DQ; h++) y += W_out[d * DQ + h] * s[h];
        out[((b * OUTD + d) * T_ + t) * V_ + v] = y;
    }
}

// ---------------------------------------------------------------------------
// Launch
// ---------------------------------------------------------------------------
extern "C" void kernel_launch(void* const* d_in, const int* in_sizes, int n_in,
                              void* d_out, int out_size) {
    const float* x       = (const float*)d_in[0];
    const float* coords  = (const float*)d_in[1];
    const float* meta    = (const float*)d_in[2];
    const float* W_ih    = (const float*)d_in[3];
    /* W_hh unused: h0 = 0 */
    const float* b_ih    = (const float*)d_in[5];
    const float* b_hh    = (const float*)d_in[6];
    const float* W_comp  = (const float*)d_in[7];
    const float* b_comp  = (const float*)d_in[8];
    const float* W_fuse  = (const float*)d_in[9];
    const float* b_fuse  = (const float*)d_in[10];
    const float* W_fc    = (const float*)d_in[11];
    const float* b_fc    = (const float*)d_in[12];
    const float* W_fc2   = (const float*)d_in[13];
    const float* b_fc2   = (const float*)d_in[14];
    const float* W_fc3   = (const float*)d_in[15];
    const float* b_fc3   = (const float*)d_in[16];
    const float* W_out   = (const float*)d_in[17];
    const float* b_out   = (const float*)d_in[18];
    float* out = (float*)d_out;

    k0_weff<<<dim3(8, 4), 256>>>(W_fuse, W_comp, b_comp);
    k1_pcomp<<<32, 256>>>(meta);
    k1b_reduce<<<4, 256>>>();
    k2_rows<<<80, 128>>>(x, coords, W_ih, b_ih, b_hh, W_fuse, b_fuse,
                         W_fc, b_fc, W_fc2, b_fc2, W_fc3, b_fc3);
    k3_attn<<<dim3(NQB, KSPLIT), 128>>>();
    k4_out<<<80, 128>>>(W_out, b_out, out);
}

// round 5
// speedup vs baseline: 1.1365x; 1.0526x over previous
#include <cuda_runtime.h>
#include <cuda_bf16.h>
#include <math.h>

// ---------------------------------------------------------------------------
#define B_     2
#define T_     20
#define V_     256
#define TN     (T_ * V_)          // 5120
#define NROWS  (B_ * TN)         // 10240
#define HID    4
#define DQ     8
#define OUTD   5
#define CMAP   2048
#define HMAP   32
#define WMAP   32
#define NPIX   (HMAP * WMAP)     // 1024
#define CC     256

#define KSPLIT 32
#define KCHUNK (TN / KSPLIT)     // 160
#define QBLK   512               // 128 thr x 4 q
#define NQB    (NROWS / QBLK)    // 20

#define W0SPLIT 16               // cc splits in k0
#define C1SPLIT 64               // channel chunks in k1

// ---------------------------------------------------------------------------
__device__ float  g_Weffp[W0SPLIT * 4 * CMAP];
__device__ float  g_cb[4];
__device__ float  g_pp[C1SPLIT * 4 * NPIX];
__device__ float4 g_pcomp4[NPIX];
__device__ float  g_Q[NROWS * DQ];             // pre-scaled by -log2(e)
__device__ float  g_KV[NROWS * 16];
__device__ float  g_part[KSPLIT * NROWS * DQ];

// ---------------------------------------------------------------------------
__device__ __forceinline__ float ex2f(float x) {
    float r; asm("ex2.approx.f32 %0, %1;" : "=f"(r) : "f"(x)); return r;
}
__device__ __forceinline__ float rcpf(float x) {
    float r; asm("rcp.approx.f32 %0, %1;" : "=f"(r) : "f"(x)); return r;
}
__device__ __forceinline__ float fsigm(float x) { return rcpf(1.f + ex2f(-1.44269504f * x)); }
__device__ __forceinline__ float ftanh(float x) { return 1.f - 2.f * rcpf(ex2f(2.88539008f * x) + 1.f); }

// ---------------------------------------------------------------------------
// K0: Weff partials over 16 cc-splits. grid(8, 16) x 256.
// ---------------------------------------------------------------------------
__global__ __launch_bounds__(256) void k0_weff(const float* __restrict__ W_fuse,
                                               const float* __restrict__ W_comp,
                                               const float* __restrict__ b_comp) {
    __shared__ float sw[4 * 16];
    int tid = threadIdx.x, by = blockIdx.y;
    if (tid < 64) {
        int h = tid >> 4, cc = tid & 15;
        sw[tid] = W_fuse[h * 260 + 4 + by * 16 + cc];
    }
    __syncthreads();

    int c = blockIdx.x * 256 + tid;
    float a0 = 0.f, a1 = 0.f, a2 = 0.f, a3 = 0.f;
#pragma unroll
    for (int cc = 0; cc < 16; cc++) {
        float w = W_comp[(by * 16 + cc) * CMAP + c];
        a0 += sw[cc]      * w;
        a1 += sw[16 + cc] * w;
        a2 += sw[32 + cc] * w;
        a3 += sw[48 + cc] * w;
    }
    g_Weffp[(by * 4 + 0) * CMAP + c] = a0;
    g_Weffp[(by * 4 + 1) * CMAP + c] = a1;
    g_Weffp[(by * 4 + 2) * CMAP + c] = a2;
    g_Weffp[(by * 4 + 3) * CMAP + c] = a3;

    if (blockIdx.x == 0 && by == 0 && tid < 32) {
        float p0 = 0.f, p1 = 0.f, p2 = 0.f, p3 = 0.f;
        for (int cc = tid; cc < CC; cc += 32) {
            float bv = b_comp[cc];
            p0 += W_fuse[0 * 260 + 4 + cc] * bv;
            p1 += W_fuse[1 * 260 + 4 + cc] * bv;
            p2 += W_fuse[2 * 260 + 4 + cc] * bv;
            p3 += W_fuse[3 * 260 + 4 + cc] * bv;
        }
#pragma unroll
        for (int o = 16; o > 0; o >>= 1) {
            p0 += __shfl_down_sync(0xffffffffu, p0, o);
            p1 += __shfl_down_sync(0xffffffffu, p1, o);
            p2 += __shfl_down_sync(0xffffffffu, p2, o);
            p3 += __shfl_down_sync(0xffffffffu, p3, o);
        }
        if (tid == 0) { g_cb[0] = p0; g_cb[1] = p1; g_cb[2] = p2; g_cb[3] = p3; }
    }
}

// ---------------------------------------------------------------------------
// K1: pcomp partials over 64 channel chunks of 32. grid(64) x 256.
// ---------------------------------------------------------------------------
__global__ __launch_bounds__(256) void k1_pcomp(const float* __restrict__ metadata) {
    __shared__ float sw[128];   // [h*32 + cl]
    int tid = threadIdx.x, ci = blockIdx.x;
    if (tid < 128) {
        int h = tid >> 5, cl = tid & 31;
        int c = ci * 32 + cl;
        float s = 0.f;
#pragma unroll
        for (int sp = 0; sp < W0SPLIT; sp++) s += g_Weffp[(sp * 4 + h) * CMAP + c];
        sw[tid] = s;
    }
    __syncthreads();

    const float4* m4 = (const float4*)metadata;
    float4 a0 = make_float4(0, 0, 0, 0), a1 = a0, a2 = a0, a3 = a0;
#pragma unroll 8
    for (int cl = 0; cl < 32; cl++) {
        float4 m = m4[(ci * 32 + cl) * 256 + tid];
        float w0 = sw[cl], w1 = sw[32 + cl], w2 = sw[64 + cl], w3 = sw[96 + cl];
        a0.x += w0 * m.x; a0.y += w0 * m.y; a0.z += w0 * m.z; a0.w += w0 * m.w;
        a1.x += w1 * m.x; a1.y += w1 * m.y; a1.z += w1 * m.z; a1.w += w1 * m.w;
        a2.x += w2 * m.x; a2.y += w2 * m.y; a2.z += w2 * m.z; a2.w += w2 * m.w;
        a3.x += w3 * m.x; a3.y += w3 * m.y; a3.z += w3 * m.z; a3.w += w3 * m.w;
    }
    float4* pp4 = (float4*)g_pp;
    pp4[(ci * 4 + 0) * 256 + tid] = a0;
    pp4[(ci * 4 + 1) * 256 + tid] = a1;
    pp4[(ci * 4 + 2) * 256 + tid] = a2;
    pp4[(ci * 4 + 3) * 256 + tid] = a3;
}

// ---------------------------------------------------------------------------
// K1b: reduce 64 partials + bias. grid(4) x 256.
// ---------------------------------------------------------------------------
__global__ __launch_bounds__(256) void k1b_reduce() {
    int pix = blockIdx.x * 256 + threadIdx.x;
    float s0 = g_cb[0], s1 = g_cb[1], s2 = g_cb[2], s3 = g_cb[3];
#pragma unroll 8
    for (int ci = 0; ci < C1SPLIT; ci++) {
        s0 += g_pp[(ci * 4 + 0) * NPIX + pix];
        s1 += g_pp[(ci * 4 + 1) * NPIX + pix];
        s2 += g_pp[(ci * 4 + 2) * NPIX + pix];
        s3 += g_pp[(ci * 4 + 3) * NPIX + pix];
    }
    g_pcomp4[pix] = make_float4(s0, s1, s2, s3);
}

// ---------------------------------------------------------------------------
// K2: per-row pipeline; weights staged in smem. grid(160) x 64.
// ---------------------------------------------------------------------------
__global__ __launch_bounds__(64) void k2_rows(
        const float* __restrict__ x,
        const float* __restrict__ coords,
        const float* __restrict__ W_ih,
        const float* __restrict__ b_ih,
        const float* __restrict__ b_hh,
        const float* __restrict__ W_fuse,
        const float* __restrict__ b_fuse,
        const float* __restrict__ W_fc,
        const float* __restrict__ b_fc,
        const float* __restrict__ W_fc2,
        const float* __restrict__ b_fc2,
        const float* __restrict__ W_fc3,
        const float* __restrict__ b_fc3) {
    __shared__ float sW_ih[32], sb[16], sWf4[16], sbf[4];
    __shared__ float sW_fc[32], sb_fc[8], sW2[16], sb2[8], sW3[16], sb3[8];
    int tid = threadIdx.x;
    if (tid < 32) sW_ih[tid] = W_ih[tid];
    if (tid < 16) sb[tid] = b_ih[tid] + b_hh[tid];
    if (tid < 16) sWf4[tid] = W_fuse[(tid >> 2) * 260 + (tid & 3)];
    if (tid < 4)  sbf[tid] = b_fuse[tid];
    if (tid < 32) sW_fc[tid] = W_fc[tid];
    if (tid < 8)  sb_fc[tid] = b_fc[tid];
    if (tid < 16) sW2[tid] = W_fc2[tid];
    if (tid < 8)  sb2[tid] = b_fc2[tid];
    if (tid < 16) sW3[tid] = W_fc3[tid];
    if (tid < 8)  sb3[tid] = b_fc3[tid];
    __syncthreads();

    int r = blockIdx.x * 64 + tid;
    if (r >= NROWS) return;
    int b = r / TN;
    int p = r - b * TN;
    int t = p / V_;
    int v = p - t * V_;

    float tf  = (float)t;
    float xr0 = x[r * 2 + 0] + __sinf(tf);
    float xr1 = x[r * 2 + 1] + __cosf(tf);

    float X[HID];
#pragma unroll
    for (int h = 0; h < HID; h++) {
        int ji = h, jg = 8 + h, jo = 12 + h;
        float gi = sW_ih[ji * 2] * xr0 + sW_ih[ji * 2 + 1] * xr1 + sb[ji];
        float gg = sW_ih[jg * 2] * xr0 + sW_ih[jg * 2 + 1] * xr1 + sb[jg];
        float go = sW_ih[jo * 2] * xr0 + sW_ih[jo * 2 + 1] * xr1 + sb[jo];
        float cst = fsigm(gi) * ftanh(gg);
        X[h] = fsigm(go) * ftanh(cst);
    }

    float cx = coords[((b * 2 + 0) * T_ + t) * V_ + v];
    float cy = coords[((b * 2 + 1) * T_ + t) * V_ + v];
    float fx = cx * (1.f / 16.f) - 0.5f;
    float fy = cy * (1.f / 16.f) - 0.5f;
    float x0f = floorf(fx), y0f = floorf(fy);
    int ix0 = (int)x0f, iy0 = (int)y0f;
    float wx1 = fx - x0f, wx0 = 1.f - wx1;
    float wy1 = fy - y0f, wy0 = 1.f - wy1;

    float l0 = 0.f, l1 = 0.f, l2 = 0.f, l3 = 0.f;
#pragma unroll
    for (int cyi = 0; cyi < 2; cyi++) {
#pragma unroll
        for (int cxi = 0; cxi < 2; cxi++) {
            int iy = iy0 + cyi, ix = ix0 + cxi;
            if (iy >= 0 && iy < HMAP && ix >= 0 && ix < WMAP) {
                float w = (cyi ? wy1 : wy0) * (cxi ? wx1 : wx0);
                float4 pv = g_pcomp4[iy * WMAP + ix];
                l0 += w * pv.x; l1 += w * pv.y; l2 += w * pv.z; l3 += w * pv.w;
            }
        }
    }

    float fsd[HID];
#pragma unroll
    for (int h = 0; h < HID; h++) {
        float s = sbf[h];
#pragma unroll
        for (int j = 0; j < HID; j++) s += sWf4[h * 4 + j] * X[j];
        fsd[h] = s + (h == 0 ? l0 : (h == 1 ? l1 : (h == 2 ? l2 : l3)));
    }

#pragma unroll
    for (int d = 0; d < DQ; d++) {
        float q = sb_fc[d];
#pragma unroll
        for (int h = 0; h < HID; h++) q += sW_fc[d * HID + h] * fsd[h];
        g_Q[r * DQ + d] = q * -1.44269504f;
        g_KV[r * 16 + d]     = sW2[d * 2] * xr0 + sW2[d * 2 + 1] * xr1 + sb2[d];
        g_KV[r * 16 + 8 + d] = sW3[d * 2] * xr0 + sW3[d * 2 + 1] * xr1 + sb3[d];
    }
}

// ---------------------------------------------------------------------------
// K3: fused sigmoid attention, 4 q/thread, 2 keys/iter.
// grid(20, 32) x 128. smem 10 KB.
// ---------------------------------------------------------------------------
__global__ __launch_bounds__(128) void k3_attn() {
    __shared__ float4 skv[KCHUNK * 4];
    int bq  = blockIdx.x;
    int ks  = blockIdx.y;
    int tid = threadIdx.x;
    int b   = bq / (NQB / B_);
    int kbase = b * TN + ks * KCHUNK;

    const float4* src = (const float4*)(g_KV + (size_t)kbase * 16);
#pragma unroll
    for (int i = tid; i < KCHUNK * 4; i += 128) skv[i] = src[i];
    __syncthreads();

    int r = bq * QBLK + tid * 4;

    float q[4][8];
    const float4* qv = (const float4*)(g_Q + (size_t)r * DQ);
#pragma unroll
    for (int i = 0; i < 4; i++) {
        float4 a = qv[i * 2 + 0], bb = qv[i * 2 + 1];
        q[i][0] = a.x;  q[i][1] = a.y;  q[i][2] = a.z;  q[i][3] = a.w;
        q[i][4] = bb.x; q[i][5] = bb.y; q[i][6] = bb.z; q[i][7] = bb.w;
    }

    float acc[4][8];
#pragma unroll
    for (int i = 0; i < 4; i++)
#pragma unroll
        for (int d = 0; d < 8; d++) acc[i][d] = 0.f;

#pragma unroll 2
    for (int j = 0; j < KCHUNK; j += 2) {
        float4 ka0 = skv[j * 4 + 0], ka1 = skv[j * 4 + 1];
        float4 kb0 = skv[j * 4 + 4], kb1 = skv[j * 4 + 5];
        float ka[8] = { ka0.x, ka0.y, ka0.z, ka0.w, ka1.x, ka1.y, ka1.z, ka1.w };
        float kb[8] = { kb0.x, kb0.y, kb0.z, kb0.w, kb1.x, kb1.y, kb1.z, kb1.w };

        float da[4], db[4];
#pragma unroll
        for (int i = 0; i < 4; i++) {
            float sa = q[i][0] * ka[0];
            float sb = q[i][0] * kb[0];
#pragma unroll
            for (int dd = 1; dd < 8; dd++) {
                sa += q[i][dd] * ka[dd];
                sb += q[i][dd] * kb[dd];
            }
            da[i] = sa; db[i] = sb;
        }

        // 8 independent sigmoid chains (ex2 then rcp), batched
        float ea[4], eb[4], pa[4], pb[4];
#pragma unroll
        for (int i = 0; i < 4; i++) { ea[i] = ex2f(da[i]); eb[i] = ex2f(db[i]); }
#pragma unroll
        for (int i = 0; i < 4; i++) { pa[i] = rcpf(1.f + ea[i]); pb[i] = rcpf(1.f + eb[i]); }

        float4 va0 = skv[j * 4 + 2], va1 = skv[j * 4 + 3];
        float4 vb0 = skv[j * 4 + 6], vb1 = skv[j * 4 + 7];
        float va[8] = { va0.x, va0.y, va0.z, va0.w, va1.x, va1.y, va1.z, va1.w };
        float vb[8] = { vb0.x, vb0.y, vb0.z, vb0.w, vb1.x, vb1.y, vb1.z, vb1.w };
#pragma unroll
        for (int i = 0; i < 4; i++)
#pragma unroll
            for (int dd = 0; dd < 8; dd++)
                acc[i][dd] += pa[i] * va[dd] + pb[i] * vb[dd];
    }

    float4* dst = (float4*)(g_part + ((size_t)ks * NROWS + r) * DQ);
#pragma unroll
    for (int i = 0; i < 4; i++) {
        dst[i * 2 + 0] = make_float4(acc[i][0], acc[i][1], acc[i][2], acc[i][3]);
        dst[i * 2 + 1] = make_float4(acc[i][4], acc[i][5], acc[i][6], acc[i][7]);
    }
}

// ---------------------------------------------------------------------------
// K4: reduce 32 partials, threshold, out projection. grid(80) x 128.
// ---------------------------------------------------------------------------
__global__ __launch_bounds__(128) void k4_out(const float* __restrict__ W_out,
                                              const float* __restrict__ b_out,
                                              float* __restrict__ out) {
    int r = blockIdx.x * 128 + threadIdx.x;
    if (r >= NROWS) return;

    float4 s0 = make_float4(0, 0, 0, 0), s1 = s0;
#pragma unroll 8
    for (int ksi = 0; ksi < KSPLIT; ksi++) {
        const float4* p = (const float4*)(g_part + ((size_t)ksi * NROWS + r) * DQ);
        float4 x0 = p[0], x1 = p[1];
        s0.x += x0.x; s0.y += x0.y; s0.z += x0.z; s0.w += x0.w;
        s1.x += x1.x; s1.y += x1.y; s1.z += x1.z; s1.w += x1.w;
    }
    float s[DQ] = { s0.x, s0.y, s0.z, s0.w, s1.x, s1.y, s1.z, s1.w };
#pragma unroll
    for (int d = 0; d < DQ; d++) s[d] = (s[d] > 0.5f) ? s[d] : 0.f;

    int b = r / TN;
    int p = r - b * TN;
    int t = p / V_;
    int v = p - t * V_;

#pragma unroll
    for (int d = 0; d < OUTD; d++) {
        float y = b_out[d];
#pragma unroll
        for (int h = 0; h < DQ; h++) y += W_out[d * DQ + h] * s[h];
        out[((b * OUTD + d) * T_ + t) * V_ + v] = y;
    }
}

// ---------------------------------------------------------------------------
extern "C" void kernel_launch(void* const* d_in, const int* in_sizes, int n_in,
                              void* d_out, int out_size) {
    const float* x       = (const float*)d_in[0];
    const float* coords  = (const float*)d_in[1];
    const float* meta    = (const float*)d_in[2];
    const float* W_ih    = (const float*)d_in[3];
    const float* b_ih    = (const float*)d_in[5];
    const float* b_hh    = (const float*)d_in[6];
    const float* W_comp  = (const float*)d_in[7];
    const float* b_comp  = (const float*)d_in[8];
    const float* W_fuse  = (const float*)d_in[9];
    const float* b_fuse  = (const float*)d_in[10];
    const float* W_fc    = (const float*)d_in[11];
    const float* b_fc    = (const float*)d_in[12];
    const float* W_fc2   = (const float*)d_in[13];
    const float* b_fc2   = (const float*)d_in[14];
    const float* W_fc3   = (const float*)d_in[15];
    const float* b_fc3   = (const float*)d_in[16];
    const float* W_out   = (const float*)d_in[17];
    const float* b_out   = (const float*)d_in[18];
    float* out = (float*)d_out;

    k0_weff<<<dim3(8, W0SPLIT), 256>>>(W_fuse, W_comp, b_comp);
    k1_pcomp<<<C1SPLIT, 256>>>(meta);
    k1b_reduce<<<4, 256>>>();
    k2_rows<<<160, 64>>>(x, coords, W_ih, b_ih, b_hh, W_fuse, b_fuse,
                         W_fc, b_fc, W_fc2, b_fc2, W_fc3, b_fc3);
    k3_attn<<<dim3(NQB, KSPLIT), 128>>>();
    k4_out<<<80, 128>>>(W_out, b_out, out);
}

// round 6
// speedup vs baseline: 1.7411x; 1.5320x over previous
#include <cuda_runtime.h>
#include <cuda_bf16.h>
#include <math.h>

// ---------------------------------------------------------------------------
#define B_     2
#define T_     20
#define V_     256
#define TN     (T_ * V_)          // 5120
#define NROWS  (B_ * TN)         // 10240
#define HID    4
#define DQ     8
#define OUTD   5
#define CMAP   2048
#define HMAP   32
#define WMAP   32
#define NPIX   (HMAP * WMAP)     // 1024
#define CC     256

#define KSPLIT 32
#define KCHUNK (TN / KSPLIT)     // 160
#define QPT    4                 // queries per thread in k3
#define K3THR  128
#define QBLK   (K3THR * QPT)     // 512
#define NQB    (NROWS / QBLK)    // 20

#define W0SPLIT 16
#define C1SPLIT 64

// ---------------------------------------------------------------------------
__device__ float  g_Weffp[W0SPLIT * 4 * CMAP];
__device__ float  g_cb[4];
__device__ float  g_pp[C1SPLIT * 4 * NPIX];
__device__ float4 g_pcomp4[NPIX];
__device__ float4 g_ABG[NROWS];               // (alpha,beta,gamma)*-log2e, pad
__device__ float2 g_UW[NROWS];                // pos-encoded (xr0, xr1)
__device__ float4 g_part[KSPLIT * NROWS];     // (T0,T1,T2,pad) partials

// ---------------------------------------------------------------------------
__device__ __forceinline__ float ex2f(float x) {
    float r; asm("ex2.approx.f32 %0, %1;" : "=f"(r) : "f"(x)); return r;
}
__device__ __forceinline__ float rcpf(float x) {
    float r; asm("rcp.approx.f32 %0, %1;" : "=f"(r) : "f"(x)); return r;
}
__device__ __forceinline__ float fsigm(float x) { return rcpf(1.f + ex2f(-1.44269504f * x)); }
__device__ __forceinline__ float ftanh(float x) { return 1.f - 2.f * rcpf(ex2f(2.88539008f * x) + 1.f); }

// ---------------------------------------------------------------------------
// K0: Weff partials over 16 cc-splits. grid(8, 16) x 256.
// ---------------------------------------------------------------------------
__global__ __launch_bounds__(256) void k0_weff(const float* __restrict__ W_fuse,
                                               const float* __restrict__ W_comp,
                                               const float* __restrict__ b_comp) {
    __shared__ float sw[4 * 16];
    int tid = threadIdx.x, by = blockIdx.y;
    if (tid < 64) {
        int h = tid >> 4, cc = tid & 15;
        sw[tid] = W_fuse[h * 260 + 4 + by * 16 + cc];
    }
    __syncthreads();

    int c = blockIdx.x * 256 + tid;
    float a0 = 0.f, a1 = 0.f, a2 = 0.f, a3 = 0.f;
#pragma unroll
    for (int cc = 0; cc < 16; cc++) {
        float w = W_comp[(by * 16 + cc) * CMAP + c];
        a0 += sw[cc]      * w;
        a1 += sw[16 + cc] * w;
        a2 += sw[32 + cc] * w;
        a3 += sw[48 + cc] * w;
    }
    g_Weffp[(by * 4 + 0) * CMAP + c] = a0;
    g_Weffp[(by * 4 + 1) * CMAP + c] = a1;
    g_Weffp[(by * 4 + 2) * CMAP + c] = a2;
    g_Weffp[(by * 4 + 3) * CMAP + c] = a3;

    if (blockIdx.x == 0 && by == 0 && tid < 32) {
        float p0 = 0.f, p1 = 0.f, p2 = 0.f, p3 = 0.f;
        for (int cc = tid; cc < CC; cc += 32) {
            float bv = b_comp[cc];
            p0 += W_fuse[0 * 260 + 4 + cc] * bv;
            p1 += W_fuse[1 * 260 + 4 + cc] * bv;
            p2 += W_fuse[2 * 260 + 4 + cc] * bv;
            p3 += W_fuse[3 * 260 + 4 + cc] * bv;
        }
#pragma unroll
        for (int o = 16; o > 0; o >>= 1) {
            p0 += __shfl_down_sync(0xffffffffu, p0, o);
            p1 += __shfl_down_sync(0xffffffffu, p1, o);
            p2 += __shfl_down_sync(0xffffffffu, p2, o);
            p3 += __shfl_down_sync(0xffffffffu, p3, o);
        }
        if (tid == 0) { g_cb[0] = p0; g_cb[1] = p1; g_cb[2] = p2; g_cb[3] = p3; }
    }
}

// ---------------------------------------------------------------------------
// K1: pcomp partials over 64 channel chunks of 32. grid(64) x 256.
// ---------------------------------------------------------------------------
__global__ __launch_bounds__(256) void k1_pcomp(const float* __restrict__ metadata) {
    __shared__ float sw[128];
    int tid = threadIdx.x, ci = blockIdx.x;
    if (tid < 128) {
        int h = tid >> 5, cl = tid & 31;
        int c = ci * 32 + cl;
        float s = 0.f;
#pragma unroll
        for (int sp = 0; sp < W0SPLIT; sp++) s += g_Weffp[(sp * 4 + h) * CMAP + c];
        sw[tid] = s;
    }
    __syncthreads();

    const float4* m4 = (const float4*)metadata;
    float4 a0 = make_float4(0, 0, 0, 0), a1 = a0, a2 = a0, a3 = a0;
#pragma unroll 8
    for (int cl = 0; cl < 32; cl++) {
        float4 m = m4[(ci * 32 + cl) * 256 + tid];
        float w0 = sw[cl], w1 = sw[32 + cl], w2 = sw[64 + cl], w3 = sw[96 + cl];
        a0.x += w0 * m.x; a0.y += w0 * m.y; a0.z += w0 * m.z; a0.w += w0 * m.w;
        a1.x += w1 * m.x; a1.y += w1 * m.y; a1.z += w1 * m.z; a1.w += w1 * m.w;
        a2.x += w2 * m.x; a2.y += w2 * m.y; a2.z += w2 * m.z; a2.w += w2 * m.w;
        a3.x += w3 * m.x; a3.y += w3 * m.y; a3.z += w3 * m.z; a3.w += w3 * m.w;
    }
    float4* pp4 = (float4*)g_pp;
    pp4[(ci * 4 + 0) * 256 + tid] = a0;
    pp4[(ci * 4 + 1) * 256 + tid] = a1;
    pp4[(ci * 4 + 2) * 256 + tid] = a2;
    pp4[(ci * 4 + 3) * 256 + tid] = a3;
}

// ---------------------------------------------------------------------------
// K1b: reduce 64 partials + bias. grid(4) x 256.
// ---------------------------------------------------------------------------
__global__ __launch_bounds__(256) void k1b_reduce() {
    int pix = blockIdx.x * 256 + threadIdx.x;
    float s0 = g_cb[0], s1 = g_cb[1], s2 = g_cb[2], s3 = g_cb[3];
#pragma unroll 8
    for (int ci = 0; ci < C1SPLIT; ci++) {
        s0 += g_pp[(ci * 4 + 0) * NPIX + pix];
        s1 += g_pp[(ci * 4 + 1) * NPIX + pix];
        s2 += g_pp[(ci * 4 + 2) * NPIX + pix];
        s3 += g_pp[(ci * 4 + 3) * NPIX + pix];
    }
    g_pcomp4[pix] = make_float4(s0, s1, s2, s3);
}

// ---------------------------------------------------------------------------
// K2: per-row pos-encode, LSTM, bilinear sample, fuse, Q -> (alpha,beta,gamma)
// plus (u,w). grid(80) x 128.
// ---------------------------------------------------------------------------
__global__ __launch_bounds__(128) void k2_rows(
        const float* __restrict__ x,
        const float* __restrict__ coords,
        const float* __restrict__ W_ih,
        const float* __restrict__ b_ih,
        const float* __restrict__ b_hh,
        const float* __restrict__ W_fuse,
        const float* __restrict__ b_fuse,
        const float* __restrict__ W_fc,
        const float* __restrict__ b_fc,
        const float* __restrict__ W_fc2,
        const float* __restrict__ b_fc2) {
    __shared__ float sW_ih[32], sb[16], sWf4[16], sbf[4];
    __shared__ float sW_fc[32], sb_fc[8], sW2a[8], sW2b[8], sb2[8];
    int tid = threadIdx.x;
    if (tid < 32) sW_ih[tid] = W_ih[tid];
    if (tid < 16) sb[tid] = b_ih[tid] + b_hh[tid];
    if (tid < 16) sWf4[tid] = W_fuse[(tid >> 2) * 260 + (tid & 3)];
    if (tid < 4)  sbf[tid] = b_fuse[tid];
    if (tid < 32) sW_fc[tid] = W_fc[tid];
    if (tid < 8)  sb_fc[tid] = b_fc[tid];
    if (tid < 8)  sW2a[tid] = W_fc2[tid * 2];
    if (tid < 8)  sW2b[tid] = W_fc2[tid * 2 + 1];
    if (tid < 8)  sb2[tid] = b_fc2[tid];
    __syncthreads();

    int r = blockIdx.x * 128 + tid;
    if (r >= NROWS) return;
    int b = r / TN;
    int p = r - b * TN;
    int t = p / V_;
    int v = p - t * V_;

    float tf  = (float)t;
    float xr0 = x[r * 2 + 0] + __sinf(tf);
    float xr1 = x[r * 2 + 1] + __cosf(tf);
    g_UW[r] = make_float2(xr0, xr1);

    float X[HID];
#pragma unroll
    for (int h = 0; h < HID; h++) {
        int ji = h, jg = 8 + h, jo = 12 + h;
        float gi = sW_ih[ji * 2] * xr0 + sW_ih[ji * 2 + 1] * xr1 + sb[ji];
        float gg = sW_ih[jg * 2] * xr0 + sW_ih[jg * 2 + 1] * xr1 + sb[jg];
        float go = sW_ih[jo * 2] * xr0 + sW_ih[jo * 2 + 1] * xr1 + sb[jo];
        float cst = fsigm(gi) * ftanh(gg);
        X[h] = fsigm(go) * ftanh(cst);
    }

    float cx = coords[((b * 2 + 0) * T_ + t) * V_ + v];
    float cy = coords[((b * 2 + 1) * T_ + t) * V_ + v];
    float fx = cx * (1.f / 16.f) - 0.5f;
    float fy = cy * (1.f / 16.f) - 0.5f;
    float x0f = floorf(fx), y0f = floorf(fy);
    int ix0 = (int)x0f, iy0 = (int)y0f;
    float wx1 = fx - x0f, wx0 = 1.f - wx1;
    float wy1 = fy - y0f, wy0 = 1.f - wy1;

    float l0 = 0.f, l1 = 0.f, l2 = 0.f, l3 = 0.f;
#pragma unroll
    for (int cyi = 0; cyi < 2; cyi++) {
#pragma unroll
        for (int cxi = 0; cxi < 2; cxi++) {
            int iy = iy0 + cyi, ix = ix0 + cxi;
            if (iy >= 0 && iy < HMAP && ix >= 0 && ix < WMAP) {
                float w = (cyi ? wy1 : wy0) * (cxi ? wx1 : wx0);
                float4 pv = g_pcomp4[iy * WMAP + ix];
                l0 += w * pv.x; l1 += w * pv.y; l2 += w * pv.z; l3 += w * pv.w;
            }
        }
    }

    float fsd[HID];
#pragma unroll
    for (int h = 0; h < HID; h++) {
        float s = sbf[h];
#pragma unroll
        for (int j = 0; j < HID; j++) s += sWf4[h * 4 + j] * X[j];
        fsd[h] = s + (h == 0 ? l0 : (h == 1 ? l1 : (h == 2 ? l2 : l3)));
    }

    float al = 0.f, be = 0.f, ga = 0.f;
#pragma unroll
    for (int d = 0; d < DQ; d++) {
        float q = sb_fc[d];
#pragma unroll
        for (int h = 0; h < HID; h++) q += sW_fc[d * HID + h] * fsd[h];
        al += q * sW2a[d];
        be += q * sW2b[d];
        ga += q * sb2[d];
    }
    const float NL2E = -1.44269504f;
    g_ABG[r] = make_float4(al * NL2E, be * NL2E, ga * NL2E, 0.f);
}

// ---------------------------------------------------------------------------
// K3: rank-2 sigmoid attention. grid(NQB=20, KSPLIT=32) x 128, 4 q/thread.
// Per pair: d = a*u + b*w + g (2 FMA); pr = rcp(1+ex2(d)) (FADD+2 MUFU);
// T0+=pr, T1+=pr*u, T2+=pr*w (FADD+2 FMA).
// ---------------------------------------------------------------------------
__global__ __launch_bounds__(K3THR) void k3_attn() {
    __shared__ float2 suw[KCHUNK];
    int bq  = blockIdx.x;
    int ks  = blockIdx.y;
    int tid = threadIdx.x;
    int b   = bq / (NQB / B_);
    int kbase = b * TN + ks * KCHUNK;

    for (int i = tid; i < KCHUNK; i += K3THR) suw[i] = g_UW[kbase + i];
    __syncthreads();

    int r = bq * QBLK + tid * QPT;

    float qa[QPT], qb[QPT], qg[QPT];
#pragma unroll
    for (int i = 0; i < QPT; i++) {
        float4 abg = g_ABG[r + i];
        qa[i] = abg.x; qb[i] = abg.y; qg[i] = abg.z;
    }

    float T0[QPT], T1[QPT], T2[QPT];
#pragma unroll
    for (int i = 0; i < QPT; i++) { T0[i] = 0.f; T1[i] = 0.f; T2[i] = 0.f; }

#pragma unroll 4
    for (int j = 0; j < KCHUNK; j++) {
        float2 uw = suw[j];
        float u = uw.x, w = uw.y;
        float pr[QPT];
#pragma unroll
        for (int i = 0; i < QPT; i++) {
            float d = fmaf(qa[i], u, qg[i]);
            d = fmaf(qb[i], w, d);
            pr[i] = rcpf(1.f + ex2f(d));
        }
#pragma unroll
        for (int i = 0; i < QPT; i++) {
            T0[i] += pr[i];
            T1[i] = fmaf(pr[i], u, T1[i]);
            T2[i] = fmaf(pr[i], w, T2[i]);
        }
    }

    float4* dst = g_part + (size_t)ks * NROWS + r;
#pragma unroll
    for (int i = 0; i < QPT; i++)
        dst[i] = make_float4(T0[i], T1[i], T2[i], 0.f);
}

// ---------------------------------------------------------------------------
// K4: reduce T partials, reconstruct 8-dim, threshold, project. grid(80) x 128.
// ---------------------------------------------------------------------------
__global__ __launch_bounds__(128) void k4_out(const float* __restrict__ W_fc3,
                                              const float* __restrict__ b_fc3,
                                              const float* __restrict__ W_out,
                                              const float* __restrict__ b_out,
                                              float* __restrict__ out) {
    int r = blockIdx.x * 128 + threadIdx.x;
    if (r >= NROWS) return;

    float S0 = 0.f, S1 = 0.f, S2 = 0.f;
#pragma unroll 8
    for (int ksi = 0; ksi < KSPLIT; ksi++) {
        float4 pp = g_part[(size_t)ksi * NROWS + r];
        S0 += pp.x; S1 += pp.y; S2 += pp.z;
    }

    float s[DQ];
#pragma unroll
    for (int d = 0; d < DQ; d++) {
        float val = W_fc3[d * 2] * S1 + W_fc3[d * 2 + 1] * S2 + b_fc3[d] * S0;
        s[d] = (val > 0.5f) ? val : 0.f;
    }

    int b = r / TN;
    int p = r - b * TN;
    int t = p / V_;
    int v = p - t * V_;

#pragma unroll
    for (int d = 0; d < OUTD; d++) {
        float y = b_out[d];
#pragma unroll
        for (int h = 0; h < DQ; h++) y += W_out[d * DQ + h] * s[h];
        out[((b * OUTD + d) * T_ + t) * V_ + v] = y;
    }
}

// ---------------------------------------------------------------------------
extern "C" void kernel_launch(void* const* d_in, const int* in_sizes, int n_in,
                              void* d_out, int out_size) {
    const float* x       = (const float*)d_in[0];
    const float* coords  = (const float*)d_in[1];
    const float* meta    = (const float*)d_in[2];
    const float* W_ih    = (const float*)d_in[3];
    const float* b_ih    = (const float*)d_in[5];
    const float* b_hh    = (const float*)d_in[6];
    const float* W_comp  = (const float*)d_in[7];
    const float* b_comp  = (const float*)d_in[8];
    const float* W_fuse  = (const float*)d_in[9];
    const float* b_fuse  = (const float*)d_in[10];
    const float* W_fc    = (const float*)d_in[11];
    const float* b_fc    = (const float*)d_in[12];
    const float* W_fc2   = (const float*)d_in[13];
    const float* b_fc2   = (const float*)d_in[14];
    const float* W_fc3   = (const float*)d_in[15];
    const float* b_fc3   = (const float*)d_in[16];
    const float* W_out   = (const float*)d_in[17];
    const float* b_out   = (const float*)d_in[18];
    float* out = (float*)d_out;

    k0_weff<<<dim3(8, W0SPLIT), 256>>>(W_fuse, W_comp, b_comp);
    k1_pcomp<<<C1SPLIT, 256>>>(meta);
    k1b_reduce<<<4, 256>>>();
    k2_rows<<<80, 128>>>(x, coords, W_ih, b_ih, b_hh, W_fuse, b_fuse,
                         W_fc, b_fc, W_fc2, b_fc2);
    k3_attn<<<dim3(NQB, KSPLIT), K3THR>>>();
    k4_out<<<80, 128>>>(W_fc3, b_fc3, W_out, b_out, out);
}